// round 2
// baseline (speedup 1.0000x reference)
#include <cuda_runtime.h>

#define BB 64
#define HH 1024
#define TT 1024
#define VV 32000
#define NCHUNK 16
#define TPC (TT / NCHUNK)   // 64 timesteps per attention chunk

// ---------------- scratch (no allocs allowed) ----------------
__device__ float g_emb[BB * HH];
__device__ float g_gx[BB * 3 * HH];
__device__ float g_gh[BB * 3 * HH];
__device__ float g_concat_in[BB * 2 * HH];
__device__ float g_concat_out[BB * HH];
__device__ float g_scores[BB * TT];
__device__ float g_am[NCHUNK * BB];
__device__ float g_as[NCHUNK * BB];
__device__ float g_cctx[NCHUNK * BB * HH];
__device__ float g_cpart[2 * BB * VV];   // 16.4 MB partial buffer (max user: out gemm ksplit=2)

// ---------------- packed dual-FMA (sm_103a) ----------------
__device__ __forceinline__ void ffma2(unsigned long long& d, unsigned long long a, unsigned long long b) {
    asm("fma.rn.f32x2 %0, %1, %2, %0;" : "+l"(d) : "l"(a), "l"(b));
}

// ---------------- embedding gather ----------------
__global__ void k_embed(const int* __restrict__ seq, const float* __restrict__ table) {
    int i = blockIdx.x * 256 + threadIdx.x;       // B*H = 65536
    int b = i >> 10;
    int h = i & 1023;
    g_emb[i] = table[(long)seq[b] * HH + h];
}

// ---------------- GEMM: Cp[z*gridDim.y + ysplit][b][n] = X[64,K] @ W[N,K]^T ----------------
// Block tile 64(B) x 128(N), 256 threads, micro-tile 4b x 8n via fma.rn.f32x2.
// X is stored duplicated in smem so (x,x) pairs load directly with LDS.128.
__global__ void __launch_bounds__(256) k_gemm2(
    const float* __restrict__ X0, const float* __restrict__ W0,
    const float* __restrict__ X1, const float* __restrict__ W1,
    float* __restrict__ Cp, int N, int K, int kpb)
{
    __shared__ float Xd[16][132];   // [k][2*b] duplicated pairs, stride 132 (16B-aligned, conflict-reducing)
    __shared__ float Ws[16][132];   // [k][n]
    const float* X = blockIdx.z ? X1 : X0;
    const float* W = blockIdx.z ? W1 : W0;
    int t  = threadIdx.x;
    int n0 = blockIdx.x * 128;
    int kb = blockIdx.y * kpb;

    unsigned long long acc[4][4];
#pragma unroll
    for (int i = 0; i < 4; i++)
#pragma unroll
        for (int j = 0; j < 4; j++) acc[i][j] = 0ull;

    int tb = (t & 15) * 4;      // b-base of micro tile
    int tn = (t >> 4) * 8;      // n-base of micro tile
    int xr = t >> 2, xk = (t & 3) * 4;

    for (int k0 = kb; k0 < kb + kpb; k0 += 16) {
        // X fill: 64 rows x 16 k = 256 float4, one per thread, duplicated store
        float4 xv = *(const float4*)&X[(size_t)xr * K + k0 + xk];
        Xd[xk + 0][2 * xr] = xv.x; Xd[xk + 0][2 * xr + 1] = xv.x;
        Xd[xk + 1][2 * xr] = xv.y; Xd[xk + 1][2 * xr + 1] = xv.y;
        Xd[xk + 2][2 * xr] = xv.z; Xd[xk + 2][2 * xr + 1] = xv.z;
        Xd[xk + 3][2 * xr] = xv.w; Xd[xk + 3][2 * xr + 1] = xv.w;
        // W fill: 128 rows x 16 k = 512 float4, two per thread
#pragma unroll
        for (int i = 0; i < 2; i++) {
            int idx = t + i * 256;
            int r = idx >> 2, kc = (idx & 3) * 4;
            float4 v = *(const float4*)&W[(size_t)(n0 + r) * K + k0 + kc];
            Ws[kc + 0][r] = v.x; Ws[kc + 1][r] = v.y; Ws[kc + 2][r] = v.z; Ws[kc + 3][r] = v.w;
        }
        __syncthreads();
#pragma unroll
        for (int kk = 0; kk < 16; kk++) {
            ulonglong2 a01 = *(const ulonglong2*)&Xd[kk][2 * tb];       // (x0,x0),(x1,x1)
            ulonglong2 a23 = *(const ulonglong2*)&Xd[kk][2 * tb + 4];   // (x2,x2),(x3,x3)
            ulonglong2 b01 = *(const ulonglong2*)&Ws[kk][tn];           // (w0,w1),(w2,w3)
            ulonglong2 b23 = *(const ulonglong2*)&Ws[kk][tn + 4];       // (w4,w5),(w6,w7)
            ffma2(acc[0][0], a01.x, b01.x); ffma2(acc[0][1], a01.x, b01.y);
            ffma2(acc[0][2], a01.x, b23.x); ffma2(acc[0][3], a01.x, b23.y);
            ffma2(acc[1][0], a01.y, b01.x); ffma2(acc[1][1], a01.y, b01.y);
            ffma2(acc[1][2], a01.y, b23.x); ffma2(acc[1][3], a01.y, b23.y);
            ffma2(acc[2][0], a23.x, b01.x); ffma2(acc[2][1], a23.x, b01.y);
            ffma2(acc[2][2], a23.x, b23.x); ffma2(acc[2][3], a23.x, b23.y);
            ffma2(acc[3][0], a23.y, b01.x); ffma2(acc[3][1], a23.y, b01.y);
            ffma2(acc[3][2], a23.y, b23.x); ffma2(acc[3][3], a23.y, b23.y);
        }
        __syncthreads();
    }

    float* outp = Cp + ((size_t)blockIdx.z * gridDim.y + blockIdx.y) * ((size_t)BB * N);
#pragma unroll
    for (int i = 0; i < 4; i++) {
        union { unsigned long long u; float2 f; } u0, u1, u2, u3;
        u0.u = acc[i][0]; u1.u = acc[i][1]; u2.u = acc[i][2]; u3.u = acc[i][3];
        float4 v0 = make_float4(u0.f.x, u0.f.y, u1.f.x, u1.f.y);
        float4 v1 = make_float4(u2.f.x, u2.f.y, u3.f.x, u3.f.y);
        *(float4*)&outp[(size_t)(tb + i) * N + n0 + tn]     = v0;
        *(float4*)&outp[(size_t)(tb + i) * N + n0 + tn + 4] = v1;
    }
}

// ---------------- combine splits + bias + optional tanh ----------------
__global__ void k_combine(const float* __restrict__ Cp, const float* __restrict__ bias,
                          float* __restrict__ C, int N, int ksplit, int act) {
    int i = blockIdx.x * 256 + threadIdx.x;
    float v = 0.f;
    for (int s = 0; s < ksplit; s++) v += Cp[(size_t)s * (BB * N) + i];
    v += bias[i % N];
    if (act) v = tanhf(v);
    C[i] = v;
}

// ---------------- GRU gates ----------------
__global__ void k_gate(const float* __restrict__ last_hidden, float* __restrict__ out_hidden) {
    int i = blockIdx.x * 256 + threadIdx.x;   // B*H
    int b = i >> 10;
    int h = i & 1023;
    const float* gx = g_gx + b * 3 * HH;
    const float* gh = g_gh + b * 3 * HH;
    float r = 1.f / (1.f + expf(-(gx[h] + gh[h])));
    float z = 1.f / (1.f + expf(-(gx[HH + h] + gh[HH + h])));
    float n = tanhf(gx[2 * HH + h] + r * gh[2 * HH + h]);
    float hp = last_hidden[i];
    float hn = (1.f - z) * n + z * hp;
    out_hidden[i] = hn;
    g_concat_in[b * 2 * HH + h] = hn;
}

// ---------------- fused attention: scores + online softmax + partial context ----------------
// grid (NCHUNK, B), 256 threads. Each block streams its t-range of enc ONCE.
__global__ void k_attn(const float* __restrict__ enc, const float* __restrict__ hnew) {
    int chunk = blockIdx.x, b = blockIdx.y;
    int tid = threadIdx.x;
    int h0 = tid * 4;
    __shared__ float red[8];
    __shared__ float bc2[2];
    float4 hv = *(const float4*)&hnew[b * HH + h0];
    float m = -1e30f, s = 0.f;
    float c0 = 0.f, c1 = 0.f, c2 = 0.f, c3 = 0.f;
    int t0 = chunk * TPC;
    for (int tt = 0; tt < TPC; tt++) {
        int t = t0 + tt;
        float4 ev = *(const float4*)&enc[((size_t)t * BB + b) * HH + h0];
        float p = hv.x * ev.x + hv.y * ev.y + hv.z * ev.z + hv.w * ev.w;
#pragma unroll
        for (int o = 16; o; o >>= 1) p += __shfl_xor_sync(0xffffffffu, p, o);
        if ((tid & 31) == 0) red[tid >> 5] = p;
        __syncthreads();
        if (tid == 0) {
            float score = red[0] + red[1] + red[2] + red[3] + red[4] + red[5] + red[6] + red[7];
            g_scores[b * TT + t] = score;
            float rs = 1.f;
            if (score > m) { rs = expf(m - score); m = score; }
            float w = expf(score - m);
            s = s * rs + w;
            bc2[0] = rs; bc2[1] = w;
        }
        __syncthreads();
        float rs = bc2[0], w = bc2[1];
        c0 = c0 * rs + w * ev.x;
        c1 = c1 * rs + w * ev.y;
        c2 = c2 * rs + w * ev.z;
        c3 = c3 * rs + w * ev.w;
    }
    *(float4*)&g_cctx[((size_t)chunk * BB + b) * HH + h0] = make_float4(c0, c1, c2, c3);
    if (tid == 0) { g_am[chunk * BB + b] = m; g_as[chunk * BB + b] = s; }
}

// ---------------- attention combine: merge chunk partials, emit attn + context ----------------
__global__ void k_attn_comb(float* __restrict__ attn_out) {
    int b = blockIdx.x;
    int tid = threadIdx.x;
    float f[NCHUNK];
    float mstar = -1e30f;
#pragma unroll
    for (int c = 0; c < NCHUNK; c++) mstar = fmaxf(mstar, g_am[c * BB + b]);
    float sstar = 0.f;
#pragma unroll
    for (int c = 0; c < NCHUNK; c++) {
        f[c] = expf(g_am[c * BB + b] - mstar);
        sstar += g_as[c * BB + b] * f[c];
    }
    float inv = 1.f / sstar;
    int h0 = tid * 4;
    float ax = 0.f, ay = 0.f, az = 0.f, aw = 0.f;
#pragma unroll
    for (int c = 0; c < NCHUNK; c++) {
        float4 v = *(const float4*)&g_cctx[((size_t)c * BB + b) * HH + h0];
        ax += v.x * f[c]; ay += v.y * f[c]; az += v.z * f[c]; aw += v.w * f[c];
    }
    *(float4*)&g_concat_in[b * 2 * HH + HH + h0] = make_float4(ax * inv, ay * inv, az * inv, aw * inv);
#pragma unroll
    for (int j = 0; j < 4; j++) {
        int t = tid + j * 256;
        attn_out[b * TT + t] = expf(g_scores[b * TT + t] - mstar) * inv;
    }
}

// ---------------- launcher ----------------
extern "C" void kernel_launch(void* const* d_in, const int* in_sizes, int n_in,
                              void* d_out, int out_size) {
    const int*   seq         = (const int*)d_in[0];
    const float* last_hidden = (const float*)d_in[1];
    const float* enc         = (const float*)d_in[2];
    const float* emb_table   = (const float*)d_in[3];
    const float* w_ih        = (const float*)d_in[4];
    const float* w_hh        = (const float*)d_in[5];
    const float* b_ih        = (const float*)d_in[6];
    const float* b_hh        = (const float*)d_in[7];
    const float* concat_W    = (const float*)d_in[8];
    const float* concat_b    = (const float*)d_in[9];
    const float* out_W       = (const float*)d_in[10];
    const float* out_b       = (const float*)d_in[11];

    float* out        = (float*)d_out;             // [B, V]
    float* out_hidden = out + BB * VV;             // [1, B, H]
    float* out_attn   = out + BB * VV + BB * HH;   // [B, 1, T]

    float *p_emb, *p_gx, *p_gh, *p_cin, *p_cout, *p_cp;
    cudaGetSymbolAddress((void**)&p_emb,  g_emb);
    cudaGetSymbolAddress((void**)&p_gx,   g_gx);
    cudaGetSymbolAddress((void**)&p_gh,   g_gh);
    cudaGetSymbolAddress((void**)&p_cin,  g_concat_in);
    cudaGetSymbolAddress((void**)&p_cout, g_concat_out);
    cudaGetSymbolAddress((void**)&p_cp,   g_cpart);

    // 1. embedding
    k_embed<<<256, 256>>>(seq, emb_table);
    // 2+3. gx = emb @ w_ih^T ; gh = h @ w_hh^T   (merged, N=3072, K=1024, ksplit=4)
    k_gemm2<<<dim3(24, 4, 2), 256>>>(p_emb, w_ih, last_hidden, w_hh, p_cp, 3 * HH, HH, 256);
    k_combine<<<768, 256>>>(p_cp,                          b_ih, p_gx, 3 * HH, 4, 0);
    k_combine<<<768, 256>>>(p_cp + (size_t)4 * BB * 3 * HH, b_hh, p_gh, 3 * HH, 4, 0);
    // 4. GRU gates -> h_new (to out_hidden and concat_in[:, :H])
    k_gate<<<256, 256>>>(last_hidden, out_hidden);
    // 5. fused attention (scores + softmax + context), single enc pass
    k_attn<<<dim3(NCHUNK, BB), 256>>>(enc, out_hidden);
    k_attn_comb<<<BB, 256>>>(out_attn);
    // 6. concat_output = tanh(concat_in @ concat_W^T + concat_b)  (N=1024, K=2048, ksplit=16)
    k_gemm2<<<dim3(8, 16, 1), 256>>>(p_cin, concat_W, p_cin, concat_W, p_cp, HH, 2 * HH, 128);
    k_combine<<<256, 256>>>(p_cp, concat_b, p_cout, HH, 16, 1);
    // 7. output = concat_out @ out_W^T + out_b  (N=32000, K=1024, ksplit=2)
    k_gemm2<<<dim3(250, 2, 1), 256>>>(p_cout, out_W, p_cout, out_W, p_cp, VV, HH, 512);
    k_combine<<<8000, 256>>>(p_cp, out_b, out, VV, 2, 0);
}

// round 4
// speedup vs baseline: 1.4764x; 1.4764x over previous
#include <cuda_runtime.h>
#include <cuda_bf16.h>
#include <cstdint>

#define BB 64
#define HH 1024
#define TT 1024
#define VV 32000
#define NCHUNK 16
#define TPC (TT / NCHUNK)

// ---------------- scratch (no allocs allowed) ----------------
__device__ float g_scores[BB * TT];
__device__ float g_am[NCHUNK * BB];
__device__ float g_as[NCHUNK * BB];
__device__ float g_cctx[NCHUNK * BB * HH];
__device__ float g_cpart[2 << 20];                         // 8MB partials
__device__ __nv_bfloat16 g_embh[BB * HH], g_embl[BB * HH];
__device__ __nv_bfloat16 g_hidh[BB * HH], g_hidl[BB * HH];
__device__ __nv_bfloat16 g_cinh[BB * 2 * HH], g_cinl[BB * 2 * HH];
__device__ __nv_bfloat16 g_couth[BB * HH], g_coutl[BB * HH];

// ---------------- helpers ----------------
// pack two floats' bf16-hi parts into one bf16x2 reg, and the residuals into another
__device__ __forceinline__ void split2(float f0, float f1, uint32_t& hi, uint32_t& lo) {
    uint32_t h0 = (uint32_t)__bfloat16_as_ushort(__float2bfloat16(f0));
    uint32_t h1 = (uint32_t)__bfloat16_as_ushort(__float2bfloat16(f1));
    hi = h0 | (h1 << 16);
    float r0 = f0 - __uint_as_float(h0 << 16);
    float r1 = f1 - __uint_as_float(h1 << 16);
    uint32_t l0 = (uint32_t)__bfloat16_as_ushort(__float2bfloat16(r0));
    uint32_t l1 = (uint32_t)__bfloat16_as_ushort(__float2bfloat16(r1));
    lo = l0 | (l1 << 16);
}

#define MMA16816(D, A, B) \
    asm volatile("mma.sync.aligned.m16n8k16.row.col.f32.bf16.bf16.f32 " \
        "{%0,%1,%2,%3}, {%4,%5,%6,%7}, {%8,%9}, {%0,%1,%2,%3};" \
        : "+f"((D)[0]), "+f"((D)[1]), "+f"((D)[2]), "+f"((D)[3]) \
        : "r"((A)[0]), "r"((A)[1]), "r"((A)[2]), "r"((A)[3]), "r"((B)[0]), "r"((B)[1]))

// ---------------- HMMA GEMM: Out[ksplit][b][n] = X[64,K] @ W[N,K]^T (+bias) ----------------
// fp32 accuracy via bf16 hi/lo split: ah*bh + ah*bl + al*bh.
// grid (Ntot/128, ksplit, z), 128 threads (4 warps), warp tile 32n x 64b.
__global__ void __launch_bounds__(128) k_hmma(
    const float* __restrict__ W0, const float* __restrict__ W1,
    const __nv_bfloat16* __restrict__ Xh0, const __nv_bfloat16* __restrict__ Xl0,
    const __nv_bfloat16* __restrict__ Xh1, const __nv_bfloat16* __restrict__ Xl1,
    float* __restrict__ Out0, float* __restrict__ Out1,
    const float* __restrict__ bias0, const float* __restrict__ bias1,
    int K, int use_bias)
{
    const float* W = blockIdx.z ? W1 : W0;
    const __nv_bfloat16* Xh = blockIdx.z ? Xh1 : Xh0;
    const __nv_bfloat16* Xl = blockIdx.z ? Xl1 : Xl0;
    float* Out = blockIdx.z ? Out1 : Out0;
    const float* bias = blockIdx.z ? bias1 : bias0;

    const int Ntot = gridDim.x * 128;
    const int w = threadIdx.x >> 5, l = threadIdx.x & 31;
    const int grp = l >> 2, qid = l & 3;
    const int n0 = blockIdx.x * 128 + w * 32;
    const int kpb = K / gridDim.y;
    const int k0b = blockIdx.y * kpb;
    Out += (size_t)blockIdx.y * ((size_t)BB * Ntot);

    float acc[2][8][4] = {};

    const float* Wp = W + (size_t)(n0 + grp) * K + k0b + qid * 2;

    for (int kk = 0; kk < kpb; kk += 16) {
        // B fragments: bf16x2 direct loads (X pre-split)
        uint32_t bh[8][2], bl[8][2];
#pragma unroll
        for (int bf = 0; bf < 8; bf++) {
            size_t off = (size_t)(bf * 8 + grp) * K + k0b + kk + qid * 2;
            bh[bf][0] = *(const uint32_t*)(Xh + off);
            bh[bf][1] = *(const uint32_t*)(Xh + off + 8);
            bl[bf][0] = *(const uint32_t*)(Xl + off);
            bl[bf][1] = *(const uint32_t*)(Xl + off + 8);
        }
#pragma unroll
        for (int mf = 0; mf < 2; mf++) {
            // A fragment: fp32 load + register split
            const float* p = Wp + (size_t)mf * 16 * K + kk;
            float2 f0 = *(const float2*)(p);
            float2 f1 = *(const float2*)(p + (size_t)8 * K);
            float2 f2 = *(const float2*)(p + 8);
            float2 f3 = *(const float2*)(p + (size_t)8 * K + 8);
            uint32_t ah[4], al[4];
            split2(f0.x, f0.y, ah[0], al[0]);
            split2(f1.x, f1.y, ah[1], al[1]);
            split2(f2.x, f2.y, ah[2], al[2]);
            split2(f3.x, f3.y, ah[3], al[3]);
#pragma unroll
            for (int bf = 0; bf < 8; bf++) {
                MMA16816(acc[mf][bf], ah, bh[bf]);
                MMA16816(acc[mf][bf], ah, bl[bf]);
                MMA16816(acc[mf][bf], al, bh[bf]);
            }
        }
    }

    // epilogue: d0->(b,n) d1->(b+1,n) d2->(b,n+8) d3->(b+1,n+8)
#pragma unroll
    for (int mf = 0; mf < 2; mf++) {
        int n = n0 + mf * 16 + grp;
        float bv0 = use_bias ? bias[n] : 0.f;
        float bv8 = use_bias ? bias[n + 8] : 0.f;
#pragma unroll
        for (int bf = 0; bf < 8; bf++) {
            int b = bf * 8 + qid * 2;
            Out[(size_t)b * Ntot + n]           = acc[mf][bf][0] + bv0;
            Out[(size_t)(b + 1) * Ntot + n]     = acc[mf][bf][1] + bv0;
            Out[(size_t)b * Ntot + n + 8]       = acc[mf][bf][2] + bv8;
            Out[(size_t)(b + 1) * Ntot + n + 8] = acc[mf][bf][3] + bv8;
        }
    }
}

// ---------------- prep: embedding gather + hidden, both split to bf16 hi/lo ----------------
__global__ void k_prep(const int* __restrict__ seq, const float* __restrict__ table,
                       const float* __restrict__ last_hidden) {
    int i = blockIdx.x * 256 + threadIdx.x;   // B*H
    int b = i >> 10, h = i & 1023;
    float e = table[(size_t)seq[b] * HH + h];
    __nv_bfloat16 eh = __float2bfloat16(e);
    g_embh[i] = eh;
    g_embl[i] = __float2bfloat16(e - __bfloat162float(eh));
    float hd = last_hidden[i];
    __nv_bfloat16 hh = __float2bfloat16(hd);
    g_hidh[i] = hh;
    g_hidl[i] = __float2bfloat16(hd - __bfloat162float(hh));
}

// ---------------- GRU gates (4-way partial combine + bias folded) ----------------
__global__ void k_gate(const float* __restrict__ last_hidden, float* __restrict__ out_hidden,
                       const float* __restrict__ b_ih, const float* __restrict__ b_hh) {
    int i = blockIdx.x * 256 + threadIdx.x;   // B*H
    int b = i >> 10, h = i & 1023;
    const float* cpA = g_cpart;                        // gx partials [4][B][3H]
    const float* cpB = g_cpart + 4 * BB * 3 * HH;      // gh partials [4][B][3H]
    const int S = BB * 3 * HH;
    int base = b * 3 * HH;
    float xr = b_ih[h], xz = b_ih[HH + h], xn = b_ih[2 * HH + h];
    float hr = b_hh[h], hz = b_hh[HH + h], hn = b_hh[2 * HH + h];
#pragma unroll
    for (int s = 0; s < 4; s++) {
        xr += cpA[s * S + base + h];
        xz += cpA[s * S + base + HH + h];
        xn += cpA[s * S + base + 2 * HH + h];
        hr += cpB[s * S + base + h];
        hz += cpB[s * S + base + HH + h];
        hn += cpB[s * S + base + 2 * HH + h];
    }
    float r = 1.f / (1.f + expf(-(xr + hr)));
    float z = 1.f / (1.f + expf(-(xz + hz)));
    float n = tanhf(xn + r * hn);
    float hnew = (1.f - z) * n + z * last_hidden[i];
    out_hidden[i] = hnew;
    __nv_bfloat16 chi = __float2bfloat16(hnew);
    g_cinh[b * 2 * HH + h] = chi;
    g_cinl[b * 2 * HH + h] = __float2bfloat16(hnew - __bfloat162float(chi));
}

// ---------------- fused attention: scores + online softmax + partial context ----------------
__global__ void k_attn(const float* __restrict__ enc, const float* __restrict__ hnew) {
    int chunk = blockIdx.x, b = blockIdx.y;
    int tid = threadIdx.x;
    int h0 = tid * 4;
    __shared__ float red[8];
    __shared__ float bc2[2];
    float4 hv = *(const float4*)&hnew[b * HH + h0];
    float m = -1e30f, s = 0.f;
    float c0 = 0.f, c1 = 0.f, c2 = 0.f, c3 = 0.f;
    int t0 = chunk * TPC;
    for (int tt = 0; tt < TPC; tt++) {
        int t = t0 + tt;
        float4 ev = *(const float4*)&enc[((size_t)t * BB + b) * HH + h0];
        float p = hv.x * ev.x + hv.y * ev.y + hv.z * ev.z + hv.w * ev.w;
#pragma unroll
        for (int o = 16; o; o >>= 1) p += __shfl_xor_sync(0xffffffffu, p, o);
        if ((tid & 31) == 0) red[tid >> 5] = p;
        __syncthreads();
        if (tid == 0) {
            float score = red[0] + red[1] + red[2] + red[3] + red[4] + red[5] + red[6] + red[7];
            g_scores[b * TT + t] = score;
            float rs = 1.f;
            if (score > m) { rs = expf(m - score); m = score; }
            float wgt = expf(score - m);
            s = s * rs + wgt;
            bc2[0] = rs; bc2[1] = wgt;
        }
        __syncthreads();
        float rs = bc2[0], wgt = bc2[1];
        c0 = c0 * rs + wgt * ev.x;
        c1 = c1 * rs + wgt * ev.y;
        c2 = c2 * rs + wgt * ev.z;
        c3 = c3 * rs + wgt * ev.w;
    }
    *(float4*)&g_cctx[((size_t)chunk * BB + b) * HH + h0] = make_float4(c0, c1, c2, c3);
    if (tid == 0) { g_am[chunk * BB + b] = m; g_as[chunk * BB + b] = s; }
}

// ---------------- attention combine: merge partials, emit attn + bf16 context ----------------
__global__ void k_attn_comb(float* __restrict__ attn_out) {
    int b = blockIdx.x;
    int tid = threadIdx.x;
    float f[NCHUNK];
    float mstar = -1e30f;
#pragma unroll
    for (int c = 0; c < NCHUNK; c++) mstar = fmaxf(mstar, g_am[c * BB + b]);
    float sstar = 0.f;
#pragma unroll
    for (int c = 0; c < NCHUNK; c++) {
        f[c] = expf(g_am[c * BB + b] - mstar);
        sstar += g_as[c * BB + b] * f[c];
    }
    float inv = 1.f / sstar;
    int h0 = tid * 4;
    float a[4] = {0.f, 0.f, 0.f, 0.f};
#pragma unroll
    for (int c = 0; c < NCHUNK; c++) {
        float4 v = *(const float4*)&g_cctx[((size_t)c * BB + b) * HH + h0];
        a[0] += v.x * f[c]; a[1] += v.y * f[c]; a[2] += v.z * f[c]; a[3] += v.w * f[c];
    }
#pragma unroll
    for (int j = 0; j < 4; j++) {
        float cv = a[j] * inv;
        __nv_bfloat16 ch = __float2bfloat16(cv);
        g_cinh[b * 2 * HH + HH + h0 + j] = ch;
        g_cinl[b * 2 * HH + HH + h0 + j] = __float2bfloat16(cv - __bfloat162float(ch));
    }
#pragma unroll
    for (int j = 0; j < 4; j++) {
        int t = tid + j * 256;
        attn_out[b * TT + t] = expf(g_scores[b * TT + t] - mstar) * inv;
    }
}

// ---------------- concat combine: sum 8 partials + bias -> tanh -> bf16 hi/lo ----------------
__global__ void k_comb_concat(const float* __restrict__ concat_b) {
    int i = blockIdx.x * 256 + threadIdx.x;   // B*H
    int n = i & 1023;
    float v = concat_b[n];
#pragma unroll
    for (int s = 0; s < 8; s++) v += g_cpart[s * BB * HH + i];
    v = tanhf(v);
    __nv_bfloat16 hv = __float2bfloat16(v);
    g_couth[i] = hv;
    g_coutl[i] = __float2bfloat16(v - __bfloat162float(hv));
}

// ---------------- launcher ----------------
extern "C" void kernel_launch(void* const* d_in, const int* in_sizes, int n_in,
                              void* d_out, int out_size) {
    const int*   seq         = (const int*)d_in[0];
    const float* last_hidden = (const float*)d_in[1];
    const float* enc         = (const float*)d_in[2];
    const float* emb_table   = (const float*)d_in[3];
    const float* w_ih        = (const float*)d_in[4];
    const float* w_hh        = (const float*)d_in[5];
    const float* b_ih        = (const float*)d_in[6];
    const float* b_hh        = (const float*)d_in[7];
    const float* concat_W    = (const float*)d_in[8];
    const float* concat_b    = (const float*)d_in[9];
    const float* out_W       = (const float*)d_in[10];
    const float* out_b       = (const float*)d_in[11];

    float* out        = (float*)d_out;             // [B, V]
    float* out_hidden = out + BB * VV;             // [1, B, H]
    float* out_attn   = out + BB * VV + BB * HH;   // [B, 1, T]

    float* p_cp;
    __nv_bfloat16 *p_embh, *p_embl, *p_hidh, *p_hidl, *p_cinh, *p_cinl, *p_couth, *p_coutl;
    cudaGetSymbolAddress((void**)&p_cp,    g_cpart);
    cudaGetSymbolAddress((void**)&p_embh,  g_embh);
    cudaGetSymbolAddress((void**)&p_embl,  g_embl);
    cudaGetSymbolAddress((void**)&p_hidh,  g_hidh);
    cudaGetSymbolAddress((void**)&p_hidl,  g_hidl);
    cudaGetSymbolAddress((void**)&p_cinh,  g_cinh);
    cudaGetSymbolAddress((void**)&p_cinl,  g_cinl);
    cudaGetSymbolAddress((void**)&p_couth, g_couth);
    cudaGetSymbolAddress((void**)&p_coutl, g_coutl);

    float* cpA = p_cp;                                // gx partials [4][B][3H]
    float* cpB = p_cp + 4 * BB * 3 * HH;              // gh partials [4][B][3H]

    // 1. prep: embedding + hidden -> bf16 hi/lo
    k_prep<<<256, 256>>>(seq, emb_table, last_hidden);
    // 2. gx = emb @ w_ih^T ; gh = h @ w_hh^T  (merged via z, ksplit=4, no bias)
    k_hmma<<<dim3(24, 4, 2), 128>>>(
        w_ih, w_hh, p_embh, p_embl, p_hidh, p_hidl, cpA, cpB, nullptr, nullptr, HH, 0);
    // 3. GRU gates -> h_new (folds partial-combine + bias)
    k_gate<<<256, 256>>>(last_hidden, out_hidden, b_ih, b_hh);
    // 4. fused attention, single enc pass
    k_attn<<<dim3(NCHUNK, BB), 256>>>(enc, out_hidden);
    k_attn_comb<<<BB, 256>>>(out_attn);
    // 5. concat gemm (K=2048, ksplit=8, no bias) -> partials
    k_hmma<<<dim3(8, 8, 1), 128>>>(
        concat_W, concat_W, p_cinh, p_cinl, p_cinh, p_cinl, p_cp, p_cp, nullptr, nullptr, 2 * HH, 0);
    k_comb_concat<<<256, 256>>>(concat_b);
    // 6. output gemm (K=1024, no split, bias, direct write)
    k_hmma<<<dim3(250, 1, 1), 128>>>(
        out_W, out_W, p_couth, p_coutl, p_couth, p_coutl, out, out, out_b, out_b, HH, 1);
}

// round 5
// speedup vs baseline: 1.7584x; 1.1911x over previous
#include <cuda_runtime.h>
#include <cuda_bf16.h>
#include <cstdint>

#define BB 64
#define HH 1024
#define TT 1024
#define VV 32000
#define NCHUNK 16
#define TPC (TT / NCHUNK)

// ---------------- scratch (no allocs allowed) ----------------
__device__ float g_scores[BB * TT];
__device__ float g_am[NCHUNK * BB];
__device__ float g_as[NCHUNK * BB];
__device__ float g_cctx[NCHUNK * BB * HH];
__device__ float g_cpart[2 << 20];                         // 8MB partials
__device__ __nv_bfloat16 g_embh[BB * HH], g_embl[BB * HH];
__device__ __nv_bfloat16 g_hidh[BB * HH], g_hidl[BB * HH];
__device__ __nv_bfloat16 g_cinh[BB * 2 * HH], g_cinl[BB * 2 * HH];
__device__ __nv_bfloat16 g_couth[BB * HH], g_coutl[BB * HH];

// ---------------- helpers ----------------
__device__ __forceinline__ void split2(float f0, float f1, uint32_t& hi, uint32_t& lo) {
    uint32_t h0 = (uint32_t)__bfloat16_as_ushort(__float2bfloat16(f0));
    uint32_t h1 = (uint32_t)__bfloat16_as_ushort(__float2bfloat16(f1));
    hi = h0 | (h1 << 16);
    float r0 = f0 - __uint_as_float(h0 << 16);
    float r1 = f1 - __uint_as_float(h1 << 16);
    uint32_t l0 = (uint32_t)__bfloat16_as_ushort(__float2bfloat16(r0));
    uint32_t l1 = (uint32_t)__bfloat16_as_ushort(__float2bfloat16(r1));
    lo = l0 | (l1 << 16);
}

#define MMA16816(D, A, B) \
    asm volatile("mma.sync.aligned.m16n8k16.row.col.f32.bf16.bf16.f32 " \
        "{%0,%1,%2,%3}, {%4,%5,%6,%7}, {%8,%9}, {%0,%1,%2,%3};" \
        : "+f"((D)[0]), "+f"((D)[1]), "+f"((D)[2]), "+f"((D)[3]) \
        : "r"((A)[0]), "r"((A)[1]), "r"((A)[2]), "r"((A)[3]), "r"((B)[0]), "r"((B)[1]))

// ---------------- HMMA GEMM: Out[ksplit][b][n] = X[64,K] @ W[N,K]^T (+bias) ----------------
__global__ void __launch_bounds__(128) k_hmma(
    const float* __restrict__ W0, const float* __restrict__ W1,
    const __nv_bfloat16* __restrict__ Xh0, const __nv_bfloat16* __restrict__ Xl0,
    const __nv_bfloat16* __restrict__ Xh1, const __nv_bfloat16* __restrict__ Xl1,
    float* __restrict__ Out0, float* __restrict__ Out1,
    const float* __restrict__ bias0, const float* __restrict__ bias1,
    int K, int use_bias)
{
    const float* W = blockIdx.z ? W1 : W0;
    const __nv_bfloat16* Xh = blockIdx.z ? Xh1 : Xh0;
    const __nv_bfloat16* Xl = blockIdx.z ? Xl1 : Xl0;
    float* Out = blockIdx.z ? Out1 : Out0;
    const float* bias = blockIdx.z ? bias1 : bias0;

    const int Ntot = gridDim.x * 128;
    const int w = threadIdx.x >> 5, l = threadIdx.x & 31;
    const int grp = l >> 2, qid = l & 3;
    const int n0 = blockIdx.x * 128 + w * 32;
    const int kpb = K / gridDim.y;
    const int k0b = blockIdx.y * kpb;
    Out += (size_t)blockIdx.y * ((size_t)BB * Ntot);

    float acc[2][8][4] = {};

    const float* Wp = W + (size_t)(n0 + grp) * K + k0b + qid * 2;

#pragma unroll 2
    for (int kk = 0; kk < kpb; kk += 16) {
        uint32_t bh[8][2], bl[8][2];
#pragma unroll
        for (int bf = 0; bf < 8; bf++) {
            size_t off = (size_t)(bf * 8 + grp) * K + k0b + kk + qid * 2;
            bh[bf][0] = *(const uint32_t*)(Xh + off);
            bh[bf][1] = *(const uint32_t*)(Xh + off + 8);
            bl[bf][0] = *(const uint32_t*)(Xl + off);
            bl[bf][1] = *(const uint32_t*)(Xl + off + 8);
        }
#pragma unroll
        for (int mf = 0; mf < 2; mf++) {
            const float* p = Wp + (size_t)mf * 16 * K + kk;
            float2 f0 = *(const float2*)(p);
            float2 f1 = *(const float2*)(p + (size_t)8 * K);
            float2 f2 = *(const float2*)(p + 8);
            float2 f3 = *(const float2*)(p + (size_t)8 * K + 8);
            uint32_t ah[4], al[4];
            split2(f0.x, f0.y, ah[0], al[0]);
            split2(f1.x, f1.y, ah[1], al[1]);
            split2(f2.x, f2.y, ah[2], al[2]);
            split2(f3.x, f3.y, ah[3], al[3]);
#pragma unroll
            for (int bf = 0; bf < 8; bf++) {
                MMA16816(acc[mf][bf], ah, bh[bf]);
                MMA16816(acc[mf][bf], ah, bl[bf]);
                MMA16816(acc[mf][bf], al, bh[bf]);
            }
        }
    }

#pragma unroll
    for (int mf = 0; mf < 2; mf++) {
        int n = n0 + mf * 16 + grp;
        float bv0 = use_bias ? bias[n] : 0.f;
        float bv8 = use_bias ? bias[n + 8] : 0.f;
#pragma unroll
        for (int bf = 0; bf < 8; bf++) {
            int b = bf * 8 + qid * 2;
            Out[(size_t)b * Ntot + n]           = acc[mf][bf][0] + bv0;
            Out[(size_t)(b + 1) * Ntot + n]     = acc[mf][bf][1] + bv0;
            Out[(size_t)b * Ntot + n + 8]       = acc[mf][bf][2] + bv8;
            Out[(size_t)(b + 1) * Ntot + n + 8] = acc[mf][bf][3] + bv8;
        }
    }
}

// ---------------- prep: embedding gather + hidden, both split to bf16 hi/lo ----------------
__global__ void k_prep(const int* __restrict__ seq, const float* __restrict__ table,
                       const float* __restrict__ last_hidden) {
    int i = blockIdx.x * 256 + threadIdx.x;   // B*H
    int b = i >> 10, h = i & 1023;
    float e = table[(size_t)seq[b] * HH + h];
    __nv_bfloat16 eh = __float2bfloat16(e);
    g_embh[i] = eh;
    g_embl[i] = __float2bfloat16(e - __bfloat162float(eh));
    float hd = last_hidden[i];
    __nv_bfloat16 hh = __float2bfloat16(hd);
    g_hidh[i] = hh;
    g_hidl[i] = __float2bfloat16(hd - __bfloat162float(hh));
}

// ---------------- GRU gates (4-way partial combine + bias folded) ----------------
__global__ void k_gate(const float* __restrict__ last_hidden, float* __restrict__ out_hidden,
                       const float* __restrict__ b_ih, const float* __restrict__ b_hh) {
    int i = blockIdx.x * 256 + threadIdx.x;   // B*H
    int b = i >> 10, h = i & 1023;
    const float* cpA = g_cpart;                        // gx partials [4][B][3H]
    const float* cpB = g_cpart + 4 * BB * 3 * HH;      // gh partials [4][B][3H]
    const int S = BB * 3 * HH;
    int base = b * 3 * HH;
    float xr = b_ih[h], xz = b_ih[HH + h], xn = b_ih[2 * HH + h];
    float hr = b_hh[h], hz = b_hh[HH + h], hn = b_hh[2 * HH + h];
#pragma unroll
    for (int s = 0; s < 4; s++) {
        xr += cpA[s * S + base + h];
        xz += cpA[s * S + base + HH + h];
        xn += cpA[s * S + base + 2 * HH + h];
        hr += cpB[s * S + base + h];
        hz += cpB[s * S + base + HH + h];
        hn += cpB[s * S + base + 2 * HH + h];
    }
    float r = 1.f / (1.f + expf(-(xr + hr)));
    float z = 1.f / (1.f + expf(-(xz + hz)));
    float n = tanhf(xn + r * hn);
    float hnew = (1.f - z) * n + z * last_hidden[i];
    out_hidden[i] = hnew;
    __nv_bfloat16 chi = __float2bfloat16(hnew);
    g_cinh[b * 2 * HH + h] = chi;
    g_cinl[b * 2 * HH + h] = __float2bfloat16(hnew - __bfloat162float(chi));
}

// ---------------- fused attention, 8-timestep batched online softmax ----------------
// grid (NCHUNK, B), 256 threads. 3 barriers per 8 timesteps, 8 loads in flight.
__global__ void __launch_bounds__(256) k_attn(const float* __restrict__ enc, const float* __restrict__ hnew) {
    int chunk = blockIdx.x, b = blockIdx.y;
    int tid = threadIdx.x;
    int wid = tid >> 5, lane = tid & 31;
    int h0 = tid * 4;
    __shared__ float red[8][8];       // [j][warp]
    __shared__ float score_sh[8];
    __shared__ float bc[9];           // rs, w[0..7]
    float4 hv = *(const float4*)&hnew[b * HH + h0];
    float m = -1e30f, s = 0.f;
    float c0 = 0.f, c1 = 0.f, c2 = 0.f, c3 = 0.f;
    int t0 = chunk * TPC;

    for (int tt = 0; tt < TPC; tt += 8) {
        float4 ev[8];
#pragma unroll
        for (int j = 0; j < 8; j++)
            ev[j] = *(const float4*)&enc[((size_t)(t0 + tt + j) * BB + b) * HH + h0];
        float p[8];
#pragma unroll
        for (int j = 0; j < 8; j++)
            p[j] = hv.x * ev[j].x + hv.y * ev[j].y + hv.z * ev[j].z + hv.w * ev[j].w;
#pragma unroll
        for (int o = 16; o; o >>= 1)
#pragma unroll
            for (int j = 0; j < 8; j++) p[j] += __shfl_xor_sync(0xffffffffu, p[j], o);
        if (lane == 0)
#pragma unroll
            for (int j = 0; j < 8; j++) red[j][wid] = p[j];
        __syncthreads();
        if (tid < 8) {
            float sc = red[tid][0] + red[tid][1] + red[tid][2] + red[tid][3]
                     + red[tid][4] + red[tid][5] + red[tid][6] + red[tid][7];
            score_sh[tid] = sc;
            g_scores[b * TT + t0 + tt + tid] = sc;
        }
        __syncthreads();
        if (tid == 0) {
            float bm = score_sh[0];
#pragma unroll
            for (int j = 1; j < 8; j++) bm = fmaxf(bm, score_sh[j]);
            float newm = fmaxf(m, bm);
            float rs = expf(m - newm);
            float ws = 0.f;
#pragma unroll
            for (int j = 0; j < 8; j++) { float wv = expf(score_sh[j] - newm); bc[1 + j] = wv; ws += wv; }
            s = s * rs + ws;
            m = newm;
            bc[0] = rs;
        }
        __syncthreads();
        float rs = bc[0];
        float w0 = bc[1], w1 = bc[2], w2 = bc[3], w3 = bc[4];
        float w4 = bc[5], w5 = bc[6], w6 = bc[7], w7 = bc[8];
        c0 = c0 * rs; c1 = c1 * rs; c2 = c2 * rs; c3 = c3 * rs;
        c0 += w0 * ev[0].x + w1 * ev[1].x + w2 * ev[2].x + w3 * ev[3].x
            + w4 * ev[4].x + w5 * ev[5].x + w6 * ev[6].x + w7 * ev[7].x;
        c1 += w0 * ev[0].y + w1 * ev[1].y + w2 * ev[2].y + w3 * ev[3].y
            + w4 * ev[4].y + w5 * ev[5].y + w6 * ev[6].y + w7 * ev[7].y;
        c2 += w0 * ev[0].z + w1 * ev[1].z + w2 * ev[2].z + w3 * ev[3].z
            + w4 * ev[4].z + w5 * ev[5].z + w6 * ev[6].z + w7 * ev[7].z;
        c3 += w0 * ev[0].w + w1 * ev[1].w + w2 * ev[2].w + w3 * ev[3].w
            + w4 * ev[4].w + w5 * ev[5].w + w6 * ev[6].w + w7 * ev[7].w;
        __syncthreads();   // protect red[][] reuse next iteration
    }
    *(float4*)&g_cctx[((size_t)chunk * BB + b) * HH + h0] = make_float4(c0, c1, c2, c3);
    if (tid == 0) { g_am[chunk * BB + b] = m; g_as[chunk * BB + b] = s; }
}

// ---------------- attention combine: merge partials, emit attn + bf16 context ----------------
__global__ void k_attn_comb(float* __restrict__ attn_out) {
    int b = blockIdx.x;
    int tid = threadIdx.x;
    float f[NCHUNK];
    float mstar = -1e30f;
#pragma unroll
    for (int c = 0; c < NCHUNK; c++) mstar = fmaxf(mstar, g_am[c * BB + b]);
    float sstar = 0.f;
#pragma unroll
    for (int c = 0; c < NCHUNK; c++) {
        f[c] = expf(g_am[c * BB + b] - mstar);
        sstar += g_as[c * BB + b] * f[c];
    }
    float inv = 1.f / sstar;
    int h0 = tid * 4;
    float a[4] = {0.f, 0.f, 0.f, 0.f};
#pragma unroll
    for (int c = 0; c < NCHUNK; c++) {
        float4 v = *(const float4*)&g_cctx[((size_t)c * BB + b) * HH + h0];
        a[0] += v.x * f[c]; a[1] += v.y * f[c]; a[2] += v.z * f[c]; a[3] += v.w * f[c];
    }
#pragma unroll
    for (int j = 0; j < 4; j++) {
        float cv = a[j] * inv;
        __nv_bfloat16 ch = __float2bfloat16(cv);
        g_cinh[b * 2 * HH + HH + h0 + j] = ch;
        g_cinl[b * 2 * HH + HH + h0 + j] = __float2bfloat16(cv - __bfloat162float(ch));
    }
#pragma unroll
    for (int j = 0; j < 4; j++) {
        int t = tid + j * 256;
        attn_out[b * TT + t] = expf(g_scores[b * TT + t] - mstar) * inv;
    }
}

// ---------------- concat combine: sum 8 partials + bias -> tanh -> bf16 hi/lo ----------------
__global__ void k_comb_concat(const float* __restrict__ concat_b) {
    int i = blockIdx.x * 256 + threadIdx.x;   // B*H
    int n = i & 1023;
    float v = concat_b[n];
#pragma unroll
    for (int s = 0; s < 8; s++) v += g_cpart[s * BB * HH + i];
    v = tanhf(v);
    __nv_bfloat16 hv = __float2bfloat16(v);
    g_couth[i] = hv;
    g_coutl[i] = __float2bfloat16(v - __bfloat162float(hv));
}

// ---------------- launcher ----------------
extern "C" void kernel_launch(void* const* d_in, const int* in_sizes, int n_in,
                              void* d_out, int out_size) {
    const int*   seq         = (const int*)d_in[0];
    const float* last_hidden = (const float*)d_in[1];
    const float* enc         = (const float*)d_in[2];
    const float* emb_table   = (const float*)d_in[3];
    const float* w_ih        = (const float*)d_in[4];
    const float* w_hh        = (const float*)d_in[5];
    const float* b_ih        = (const float*)d_in[6];
    const float* b_hh        = (const float*)d_in[7];
    const float* concat_W    = (const float*)d_in[8];
    const float* concat_b    = (const float*)d_in[9];
    const float* out_W       = (const float*)d_in[10];
    const float* out_b       = (const float*)d_in[11];

    float* out        = (float*)d_out;             // [B, V]
    float* out_hidden = out + BB * VV;             // [1, B, H]
    float* out_attn   = out + BB * VV + BB * HH;   // [B, 1, T]

    float* p_cp;
    __nv_bfloat16 *p_embh, *p_embl, *p_hidh, *p_hidl, *p_cinh, *p_cinl, *p_couth, *p_coutl;
    cudaGetSymbolAddress((void**)&p_cp,    g_cpart);
    cudaGetSymbolAddress((void**)&p_embh,  g_embh);
    cudaGetSymbolAddress((void**)&p_embl,  g_embl);
    cudaGetSymbolAddress((void**)&p_hidh,  g_hidh);
    cudaGetSymbolAddress((void**)&p_hidl,  g_hidl);
    cudaGetSymbolAddress((void**)&p_cinh,  g_cinh);
    cudaGetSymbolAddress((void**)&p_cinl,  g_cinl);
    cudaGetSymbolAddress((void**)&p_couth, g_couth);
    cudaGetSymbolAddress((void**)&p_coutl, g_coutl);

    float* cpA = p_cp;                                // gx partials [4][B][3H]
    float* cpB = p_cp + 4 * BB * 3 * HH;              // gh partials [4][B][3H]

    // 1. prep: embedding + hidden -> bf16 hi/lo
    k_prep<<<256, 256>>>(seq, emb_table, last_hidden);
    // 2. gx = emb @ w_ih^T ; gh = h @ w_hh^T  (merged via z, ksplit=4, no bias)
    k_hmma<<<dim3(24, 4, 2), 128>>>(
        w_ih, w_hh, p_embh, p_embl, p_hidh, p_hidl, cpA, cpB, nullptr, nullptr, HH, 0);
    // 3. GRU gates -> h_new (folds partial-combine + bias)
    k_gate<<<256, 256>>>(last_hidden, out_hidden, b_ih, b_hh);
    // 4. fused attention, single enc pass (batched online softmax)
    k_attn<<<dim3(NCHUNK, BB), 256>>>(enc, out_hidden);
    k_attn_comb<<<BB, 256>>>(out_attn);
    // 5. concat gemm (K=2048, ksplit=8, no bias) -> partials
    k_hmma<<<dim3(8, 8, 1), 128>>>(
        concat_W, concat_W, p_cinh, p_cinl, p_cinh, p_cinl, p_cp, p_cp, nullptr, nullptr, 2 * HH, 0);
    k_comb_concat<<<256, 256>>>(concat_b);
    // 6. output gemm (K=1024, no split, bias, direct write)
    k_hmma<<<dim3(250, 1, 1), 128>>>(
        out_W, out_W, p_couth, p_coutl, p_couth, p_coutl, out, out, out_b, out_b, HH, 1);
}

// round 6
// speedup vs baseline: 1.8488x; 1.0514x over previous
#include <cuda_runtime.h>
#include <cuda_bf16.h>
#include <cstdint>

#define BB 64
#define HH 1024
#define TT 1024
#define VV 32000
#define NCHUNK 16
#define TPC (TT / NCHUNK)

// ---------------- scratch (no allocs allowed) ----------------
__device__ float g_scores[BB * TT];
__device__ float g_am[NCHUNK * BB];
__device__ float g_as[NCHUNK * BB];
__device__ float g_cctx[NCHUNK * BB * HH];
__device__ float g_cpart[2 << 20];                         // 8MB partials
__device__ __nv_bfloat16 g_embh[BB * HH], g_embl[BB * HH];
__device__ __nv_bfloat16 g_hidh[BB * HH], g_hidl[BB * HH];
__device__ __nv_bfloat16 g_cinh[BB * 2 * HH], g_cinl[BB * 2 * HH];
__device__ __nv_bfloat16 g_couth[BB * HH], g_coutl[BB * HH];

// ---------------- helpers ----------------
__device__ __forceinline__ void split2(float f0, float f1, uint32_t& hi, uint32_t& lo) {
    uint32_t h0 = (uint32_t)__bfloat16_as_ushort(__float2bfloat16(f0));
    uint32_t h1 = (uint32_t)__bfloat16_as_ushort(__float2bfloat16(f1));
    hi = h0 | (h1 << 16);
    float r0 = f0 - __uint_as_float(h0 << 16);
    float r1 = f1 - __uint_as_float(h1 << 16);
    uint32_t l0 = (uint32_t)__bfloat16_as_ushort(__float2bfloat16(r0));
    uint32_t l1 = (uint32_t)__bfloat16_as_ushort(__float2bfloat16(r1));
    lo = l0 | (l1 << 16);
}

#define MMA16816(D, A, B) \
    asm volatile("mma.sync.aligned.m16n8k16.row.col.f32.bf16.bf16.f32 " \
        "{%0,%1,%2,%3}, {%4,%5,%6,%7}, {%8,%9}, {%0,%1,%2,%3};" \
        : "+f"((D)[0]), "+f"((D)[1]), "+f"((D)[2]), "+f"((D)[3]) \
        : "r"((A)[0]), "r"((A)[1]), "r"((A)[2]), "r"((A)[3]), "r"((B)[0]), "r"((B)[1]))

// load 8 float2 of W for one 16-k chunk (both 16-row m-fragments)
#define LOADW(dst, kk) do { \
    _Pragma("unroll") \
    for (int mf = 0; mf < 2; mf++) { \
        const float* p = Wp + (size_t)mf * 16 * K + (kk); \
        (dst)[mf * 4 + 0] = *(const float2*)(p); \
        (dst)[mf * 4 + 1] = *(const float2*)(p + (size_t)8 * K); \
        (dst)[mf * 4 + 2] = *(const float2*)(p + 8); \
        (dst)[mf * 4 + 3] = *(const float2*)(p + (size_t)8 * K + 8); \
    } \
} while (0)

// X loads + convert W buffer + 48 MMAs for one 16-k chunk
#define CHUNK_BODY(wsrc, kk) do { \
    uint32_t bh[8][2], bl[8][2]; \
    _Pragma("unroll") \
    for (int bf = 0; bf < 8; bf++) { \
        size_t off = (size_t)(bf * 8 + grp) * K + k0b + (kk) + qid * 2; \
        bh[bf][0] = *(const uint32_t*)(Xh + off); \
        bh[bf][1] = *(const uint32_t*)(Xh + off + 8); \
        bl[bf][0] = *(const uint32_t*)(Xl + off); \
        bl[bf][1] = *(const uint32_t*)(Xl + off + 8); \
    } \
    uint32_t ah[2][4], al[2][4]; \
    _Pragma("unroll") \
    for (int mf = 0; mf < 2; mf++) \
        _Pragma("unroll") \
        for (int j = 0; j < 4; j++) \
            split2((wsrc)[mf * 4 + j].x, (wsrc)[mf * 4 + j].y, ah[mf][j], al[mf][j]); \
    _Pragma("unroll") \
    for (int mf = 0; mf < 2; mf++) \
        _Pragma("unroll") \
        for (int bf = 0; bf < 8; bf++) { \
            MMA16816(acc[mf][bf], ah[mf], bh[bf]); \
            MMA16816(acc[mf][bf], ah[mf], bl[bf]); \
            MMA16816(acc[mf][bf], al[mf], bh[bf]); \
        } \
} while (0)

// ---------------- HMMA GEMM: Out[ksplit][b][n] = X[64,K] @ W[N,K]^T (+bias) ----------------
// Double-buffered register pipeline on the streaming W operand. kpb % 32 == 0.
__global__ void __launch_bounds__(128) k_hmma(
    const float* __restrict__ W0, const float* __restrict__ W1,
    const __nv_bfloat16* __restrict__ Xh0, const __nv_bfloat16* __restrict__ Xl0,
    const __nv_bfloat16* __restrict__ Xh1, const __nv_bfloat16* __restrict__ Xl1,
    float* __restrict__ Out0, float* __restrict__ Out1,
    const float* __restrict__ bias0, const float* __restrict__ bias1,
    int K, int use_bias)
{
    const float* W = blockIdx.z ? W1 : W0;
    const __nv_bfloat16* Xh = blockIdx.z ? Xh1 : Xh0;
    const __nv_bfloat16* Xl = blockIdx.z ? Xl1 : Xl0;
    float* Out = blockIdx.z ? Out1 : Out0;
    const float* bias = blockIdx.z ? bias1 : bias0;

    const int Ntot = gridDim.x * 128;
    const int w = threadIdx.x >> 5, l = threadIdx.x & 31;
    const int grp = l >> 2, qid = l & 3;
    const int n0 = blockIdx.x * 128 + w * 32;
    const int kpb = K / gridDim.y;
    const int k0b = blockIdx.y * kpb;
    Out += (size_t)blockIdx.y * ((size_t)BB * Ntot);

    float acc[2][8][4] = {};
    const float* Wp = W + (size_t)(n0 + grp) * K + k0b + qid * 2;

    float2 bufA[8], bufB[8];
    LOADW(bufA, 0);
    for (int kk = 0; kk < kpb; kk += 32) {
        if (kk + 16 < kpb) LOADW(bufB, kk + 16);
        CHUNK_BODY(bufA, kk);
        if (kk + 32 < kpb) LOADW(bufA, kk + 32);
        CHUNK_BODY(bufB, kk + 16);
    }

#pragma unroll
    for (int mf = 0; mf < 2; mf++) {
        int n = n0 + mf * 16 + grp;
        float bv0 = use_bias ? bias[n] : 0.f;
        float bv8 = use_bias ? bias[n + 8] : 0.f;
#pragma unroll
        for (int bf = 0; bf < 8; bf++) {
            int b = bf * 8 + qid * 2;
            Out[(size_t)b * Ntot + n]           = acc[mf][bf][0] + bv0;
            Out[(size_t)(b + 1) * Ntot + n]     = acc[mf][bf][1] + bv0;
            Out[(size_t)b * Ntot + n + 8]       = acc[mf][bf][2] + bv8;
            Out[(size_t)(b + 1) * Ntot + n + 8] = acc[mf][bf][3] + bv8;
        }
    }
}

// ---------------- prep: embedding gather + hidden, both split to bf16 hi/lo ----------------
__global__ void k_prep(const int* __restrict__ seq, const float* __restrict__ table,
                       const float* __restrict__ last_hidden) {
    int i = blockIdx.x * 256 + threadIdx.x;   // B*H
    int b = i >> 10, h = i & 1023;
    float e = table[(size_t)seq[b] * HH + h];
    __nv_bfloat16 eh = __float2bfloat16(e);
    g_embh[i] = eh;
    g_embl[i] = __float2bfloat16(e - __bfloat162float(eh));
    float hd = last_hidden[i];
    __nv_bfloat16 hh = __float2bfloat16(hd);
    g_hidh[i] = hh;
    g_hidl[i] = __float2bfloat16(hd - __bfloat162float(hh));
}

// ---------------- GRU gates (4-way partial combine + bias folded) ----------------
__global__ void k_gate(const float* __restrict__ last_hidden, float* __restrict__ out_hidden,
                       const float* __restrict__ b_ih, const float* __restrict__ b_hh) {
    int i = blockIdx.x * 256 + threadIdx.x;   // B*H
    int b = i >> 10, h = i & 1023;
    const float* cpA = g_cpart;                        // gx partials [4][B][3H]
    const float* cpB = g_cpart + 4 * BB * 3 * HH;      // gh partials [4][B][3H]
    const int S = BB * 3 * HH;
    int base = b * 3 * HH;
    float xr = b_ih[h], xz = b_ih[HH + h], xn = b_ih[2 * HH + h];
    float hr = b_hh[h], hz = b_hh[HH + h], hn = b_hh[2 * HH + h];
#pragma unroll
    for (int s = 0; s < 4; s++) {
        xr += cpA[s * S + base + h];
        xz += cpA[s * S + base + HH + h];
        xn += cpA[s * S + base + 2 * HH + h];
        hr += cpB[s * S + base + h];
        hz += cpB[s * S + base + HH + h];
        hn += cpB[s * S + base + 2 * HH + h];
    }
    float r = 1.f / (1.f + expf(-(xr + hr)));
    float z = 1.f / (1.f + expf(-(xz + hz)));
    float n = tanhf(xn + r * hn);
    float hnew = (1.f - z) * n + z * last_hidden[i];
    out_hidden[i] = hnew;
    __nv_bfloat16 chi = __float2bfloat16(hnew);
    g_cinh[b * 2 * HH + h] = chi;
    g_cinl[b * 2 * HH + h] = __float2bfloat16(hnew - __bfloat162float(chi));
}

// ---------------- fused attention, 8-timestep batched online softmax ----------------
__global__ void __launch_bounds__(256) k_attn(const float* __restrict__ enc, const float* __restrict__ hnew) {
    int chunk = blockIdx.x, b = blockIdx.y;
    int tid = threadIdx.x;
    int wid = tid >> 5, lane = tid & 31;
    int h0 = tid * 4;
    __shared__ float red[8][8];       // [j][warp]
    __shared__ float score_sh[8];
    __shared__ float bc[9];           // rs, w[0..7]
    float4 hv = *(const float4*)&hnew[b * HH + h0];
    float m = -1e30f, s = 0.f;
    float c0 = 0.f, c1 = 0.f, c2 = 0.f, c3 = 0.f;
    int t0 = chunk * TPC;

    for (int tt = 0; tt < TPC; tt += 8) {
        float4 ev[8];
#pragma unroll
        for (int j = 0; j < 8; j++)
            ev[j] = *(const float4*)&enc[((size_t)(t0 + tt + j) * BB + b) * HH + h0];
        float p[8];
#pragma unroll
        for (int j = 0; j < 8; j++)
            p[j] = hv.x * ev[j].x + hv.y * ev[j].y + hv.z * ev[j].z + hv.w * ev[j].w;
#pragma unroll
        for (int o = 16; o; o >>= 1)
#pragma unroll
            for (int j = 0; j < 8; j++) p[j] += __shfl_xor_sync(0xffffffffu, p[j], o);
        if (lane == 0)
#pragma unroll
            for (int j = 0; j < 8; j++) red[j][wid] = p[j];
        __syncthreads();
        if (tid < 8) {
            float sc = red[tid][0] + red[tid][1] + red[tid][2] + red[tid][3]
                     + red[tid][4] + red[tid][5] + red[tid][6] + red[tid][7];
            score_sh[tid] = sc;
            g_scores[b * TT + t0 + tt + tid] = sc;
        }
        __syncthreads();
        if (tid == 0) {
            float bm = score_sh[0];
#pragma unroll
            for (int j = 1; j < 8; j++) bm = fmaxf(bm, score_sh[j]);
            float newm = fmaxf(m, bm);
            float rs = expf(m - newm);
            float ws = 0.f;
#pragma unroll
            for (int j = 0; j < 8; j++) { float wv = expf(score_sh[j] - newm); bc[1 + j] = wv; ws += wv; }
            s = s * rs + ws;
            m = newm;
            bc[0] = rs;
        }
        __syncthreads();
        float rs = bc[0];
        float w0 = bc[1], w1 = bc[2], w2 = bc[3], w3 = bc[4];
        float w4 = bc[5], w5 = bc[6], w6 = bc[7], w7 = bc[8];
        c0 = c0 * rs; c1 = c1 * rs; c2 = c2 * rs; c3 = c3 * rs;
        c0 += w0 * ev[0].x + w1 * ev[1].x + w2 * ev[2].x + w3 * ev[3].x
            + w4 * ev[4].x + w5 * ev[5].x + w6 * ev[6].x + w7 * ev[7].x;
        c1 += w0 * ev[0].y + w1 * ev[1].y + w2 * ev[2].y + w3 * ev[3].y
            + w4 * ev[4].y + w5 * ev[5].y + w6 * ev[6].y + w7 * ev[7].y;
        c2 += w0 * ev[0].z + w1 * ev[1].z + w2 * ev[2].z + w3 * ev[3].z
            + w4 * ev[4].z + w5 * ev[5].z + w6 * ev[6].z + w7 * ev[7].z;
        c3 += w0 * ev[0].w + w1 * ev[1].w + w2 * ev[2].w + w3 * ev[3].w
            + w4 * ev[4].w + w5 * ev[5].w + w6 * ev[6].w + w7 * ev[7].w;
        __syncthreads();   // protect red[][] reuse next iteration
    }
    *(float4*)&g_cctx[((size_t)chunk * BB + b) * HH + h0] = make_float4(c0, c1, c2, c3);
    if (tid == 0) { g_am[chunk * BB + b] = m; g_as[chunk * BB + b] = s; }
}

// ---------------- attention combine: merge partials, emit attn + bf16 context ----------------
__global__ void k_attn_comb(float* __restrict__ attn_out) {
    int b = blockIdx.x;
    int tid = threadIdx.x;
    float f[NCHUNK];
    float mstar = -1e30f;
#pragma unroll
    for (int c = 0; c < NCHUNK; c++) mstar = fmaxf(mstar, g_am[c * BB + b]);
    float sstar = 0.f;
#pragma unroll
    for (int c = 0; c < NCHUNK; c++) {
        f[c] = expf(g_am[c * BB + b] - mstar);
        sstar += g_as[c * BB + b] * f[c];
    }
    float inv = 1.f / sstar;
    int h0 = tid * 4;
    float a[4] = {0.f, 0.f, 0.f, 0.f};
#pragma unroll
    for (int c = 0; c < NCHUNK; c++) {
        float4 v = *(const float4*)&g_cctx[((size_t)c * BB + b) * HH + h0];
        a[0] += v.x * f[c]; a[1] += v.y * f[c]; a[2] += v.z * f[c]; a[3] += v.w * f[c];
    }
#pragma unroll
    for (int j = 0; j < 4; j++) {
        float cv = a[j] * inv;
        __nv_bfloat16 ch = __float2bfloat16(cv);
        g_cinh[b * 2 * HH + HH + h0 + j] = ch;
        g_cinl[b * 2 * HH + HH + h0 + j] = __float2bfloat16(cv - __bfloat162float(ch));
    }
#pragma unroll
    for (int j = 0; j < 4; j++) {
        int t = tid + j * 256;
        attn_out[b * TT + t] = expf(g_scores[b * TT + t] - mstar) * inv;
    }
}

// ---------------- concat combine: sum 8 partials + bias -> tanh -> bf16 hi/lo ----------------
__global__ void k_comb_concat(const float* __restrict__ concat_b) {
    int i = blockIdx.x * 256 + threadIdx.x;   // B*H
    int n = i & 1023;
    float v = concat_b[n];
#pragma unroll
    for (int s = 0; s < 8; s++) v += g_cpart[s * BB * HH + i];
    v = tanhf(v);
    __nv_bfloat16 hv = __float2bfloat16(v);
    g_couth[i] = hv;
    g_coutl[i] = __float2bfloat16(v - __bfloat162float(hv));
}

// ---------------- launcher ----------------
extern "C" void kernel_launch(void* const* d_in, const int* in_sizes, int n_in,
                              void* d_out, int out_size) {
    const int*   seq         = (const int*)d_in[0];
    const float* last_hidden = (const float*)d_in[1];
    const float* enc         = (const float*)d_in[2];
    const float* emb_table   = (const float*)d_in[3];
    const float* w_ih        = (const float*)d_in[4];
    const float* w_hh        = (const float*)d_in[5];
    const float* b_ih        = (const float*)d_in[6];
    const float* b_hh        = (const float*)d_in[7];
    const float* concat_W    = (const float*)d_in[8];
    const float* concat_b    = (const float*)d_in[9];
    const float* out_W       = (const float*)d_in[10];
    const float* out_b       = (const float*)d_in[11];

    float* out        = (float*)d_out;             // [B, V]
    float* out_hidden = out + BB * VV;             // [1, B, H]
    float* out_attn   = out + BB * VV + BB * HH;   // [B, 1, T]

    float* p_cp;
    __nv_bfloat16 *p_embh, *p_embl, *p_hidh, *p_hidl, *p_cinh, *p_cinl, *p_couth, *p_coutl;
    cudaGetSymbolAddress((void**)&p_cp,    g_cpart);
    cudaGetSymbolAddress((void**)&p_embh,  g_embh);
    cudaGetSymbolAddress((void**)&p_embl,  g_embl);
    cudaGetSymbolAddress((void**)&p_hidh,  g_hidh);
    cudaGetSymbolAddress((void**)&p_hidl,  g_hidl);
    cudaGetSymbolAddress((void**)&p_cinh,  g_cinh);
    cudaGetSymbolAddress((void**)&p_cinl,  g_cinl);
    cudaGetSymbolAddress((void**)&p_couth, g_couth);
    cudaGetSymbolAddress((void**)&p_coutl, g_coutl);

    float* cpA = p_cp;                                // gx partials [4][B][3H]
    float* cpB = p_cp + 4 * BB * 3 * HH;              // gh partials [4][B][3H]

    // 1. prep: embedding + hidden -> bf16 hi/lo
    k_prep<<<256, 256>>>(seq, emb_table, last_hidden);
    // 2. gx = emb @ w_ih^T ; gh = h @ w_hh^T  (merged via z, ksplit=4, no bias)
    k_hmma<<<dim3(24, 4, 2), 128>>>(
        w_ih, w_hh, p_embh, p_embl, p_hidh, p_hidl, cpA, cpB, nullptr, nullptr, HH, 0);
    // 3. GRU gates -> h_new (folds partial-combine + bias)
    k_gate<<<256, 256>>>(last_hidden, out_hidden, b_ih, b_hh);
    // 4. fused attention, single enc pass (batched online softmax)
    k_attn<<<dim3(NCHUNK, BB), 256>>>(enc, out_hidden);
    k_attn_comb<<<BB, 256>>>(out_attn);
    // 5. concat gemm (K=2048, ksplit=8, no bias) -> partials
    k_hmma<<<dim3(8, 8, 1), 128>>>(
        concat_W, concat_W, p_cinh, p_cinl, p_cinh, p_cinl, p_cp, p_cp, nullptr, nullptr, 2 * HH, 0);
    k_comb_concat<<<256, 256>>>(concat_b);
    // 6. output gemm (K=1024, no split, bias, direct write)
    k_hmma<<<dim3(250, 1, 1), 128>>>(
        out_W, out_W, p_couth, p_coutl, p_couth, p_coutl, out, out, out_b, out_b, HH, 1);
}

// round 7
// speedup vs baseline: 2.0065x; 1.0853x over previous
#include <cuda_runtime.h>
#include <cuda_bf16.h>
#include <cstdint>

#define BB 64
#define HH 1024
#define TT 1024
#define VV 32000
#define NCHUNK 16
#define TPC (TT / NCHUNK)

// ---------------- scratch (no allocs allowed) ----------------
__device__ float g_scores[BB * TT];
__device__ float g_am[NCHUNK * BB];
__device__ float g_as[NCHUNK * BB];
__device__ float g_cctx[NCHUNK * BB * HH];
__device__ float g_cpart[2 * BB * VV];                     // 16.4MB partials
__device__ __nv_bfloat16 g_embh[BB * HH], g_embl[BB * HH];
__device__ __nv_bfloat16 g_hidh[BB * HH], g_hidl[BB * HH];
__device__ __nv_bfloat16 g_cinh[BB * 2 * HH], g_cinl[BB * 2 * HH];
__device__ __nv_bfloat16 g_couth[BB * HH], g_coutl[BB * HH];

// ---------------- helpers ----------------
__device__ __forceinline__ void split2(float f0, float f1, uint32_t& hi, uint32_t& lo) {
    uint32_t h0 = (uint32_t)__bfloat16_as_ushort(__float2bfloat16(f0));
    uint32_t h1 = (uint32_t)__bfloat16_as_ushort(__float2bfloat16(f1));
    hi = h0 | (h1 << 16);
    float r0 = f0 - __uint_as_float(h0 << 16);
    float r1 = f1 - __uint_as_float(h1 << 16);
    uint32_t l0 = (uint32_t)__bfloat16_as_ushort(__float2bfloat16(r0));
    uint32_t l1 = (uint32_t)__bfloat16_as_ushort(__float2bfloat16(r1));
    lo = l0 | (l1 << 16);
}

#define MMA16816(D, A, B) \
    asm volatile("mma.sync.aligned.m16n8k16.row.col.f32.bf16.bf16.f32 " \
        "{%0,%1,%2,%3}, {%4,%5,%6,%7}, {%8,%9}, {%0,%1,%2,%3};" \
        : "+f"((D)[0]), "+f"((D)[1]), "+f"((D)[2]), "+f"((D)[3]) \
        : "r"((A)[0]), "r"((A)[1]), "r"((A)[2]), "r"((A)[3]), "r"((B)[0]), "r"((B)[1]))

// load 8 float2 of W for one 16-k chunk (both 16-row m-fragments)
#define LOADW(dst, kk) do { \
    _Pragma("unroll") \
    for (int mf = 0; mf < 2; mf++) { \
        const float* p = Wp + (size_t)mf * 16 * K + (kk); \
        (dst)[mf * 4 + 0] = *(const float2*)(p); \
        (dst)[mf * 4 + 1] = *(const float2*)(p + (size_t)8 * K); \
        (dst)[mf * 4 + 2] = *(const float2*)(p + 8); \
        (dst)[mf * 4 + 3] = *(const float2*)(p + (size_t)8 * K + 8); \
    } \
} while (0)

// load X fragments (hi+lo) for one 16-k chunk
#define LOADX(xh, xl, kk) do { \
    _Pragma("unroll") \
    for (int bf = 0; bf < 8; bf++) { \
        size_t off = (size_t)(bf * 8 + grp) * K + k0b + (kk) + qid * 2; \
        (xh)[bf][0] = *(const uint32_t*)(Xh + off); \
        (xh)[bf][1] = *(const uint32_t*)(Xh + off + 8); \
        (xl)[bf][0] = *(const uint32_t*)(Xl + off); \
        (xl)[bf][1] = *(const uint32_t*)(Xl + off + 8); \
    } \
} while (0)

// convert W buffer + 48 MMAs for one 16-k chunk
#define CHUNK_MMA(wsrc, xh, xl) do { \
    uint32_t ah[2][4], al[2][4]; \
    _Pragma("unroll") \
    for (int mf = 0; mf < 2; mf++) \
        _Pragma("unroll") \
        for (int j = 0; j < 4; j++) \
            split2((wsrc)[mf * 4 + j].x, (wsrc)[mf * 4 + j].y, ah[mf][j], al[mf][j]); \
    _Pragma("unroll") \
    for (int mf = 0; mf < 2; mf++) \
        _Pragma("unroll") \
        for (int bf = 0; bf < 8; bf++) { \
            MMA16816(acc[mf][bf], ah[mf], (xh)[bf]); \
            MMA16816(acc[mf][bf], ah[mf], (xl)[bf]); \
            MMA16816(acc[mf][bf], al[mf], (xh)[bf]); \
        } \
} while (0)

// ---------------- HMMA GEMM: Out[ksplit][b][n] = X[64,K] @ W[N,K]^T (+bias) ----------------
// Both operands double-buffered in registers. kpb % 32 == 0.
__global__ void __launch_bounds__(128, 2) k_hmma(
    const float* __restrict__ W0, const float* __restrict__ W1,
    const __nv_bfloat16* __restrict__ Xh0, const __nv_bfloat16* __restrict__ Xl0,
    const __nv_bfloat16* __restrict__ Xh1, const __nv_bfloat16* __restrict__ Xl1,
    float* __restrict__ Out0, float* __restrict__ Out1,
    const float* __restrict__ bias0, const float* __restrict__ bias1,
    int K, int use_bias)
{
    const float* W = blockIdx.z ? W1 : W0;
    const __nv_bfloat16* Xh = blockIdx.z ? Xh1 : Xh0;
    const __nv_bfloat16* Xl = blockIdx.z ? Xl1 : Xl0;
    float* Out = blockIdx.z ? Out1 : Out0;
    const float* bias = blockIdx.z ? bias1 : bias0;

    const int Ntot = gridDim.x * 128;
    const int w = threadIdx.x >> 5, l = threadIdx.x & 31;
    const int grp = l >> 2, qid = l & 3;
    const int n0 = blockIdx.x * 128 + w * 32;
    const int kpb = K / gridDim.y;
    const int k0b = blockIdx.y * kpb;
    Out += (size_t)blockIdx.y * ((size_t)BB * Ntot);

    float acc[2][8][4] = {};
    const float* Wp = W + (size_t)(n0 + grp) * K + k0b + qid * 2;

    float2 wA[8], wB[8];
    uint32_t xhA[8][2], xlA[8][2], xhB[8][2], xlB[8][2];
    LOADW(wA, 0);
    LOADX(xhA, xlA, 0);
    for (int kk = 0; kk < kpb; kk += 32) {
        if (kk + 16 < kpb) { LOADW(wB, kk + 16); LOADX(xhB, xlB, kk + 16); }
        CHUNK_MMA(wA, xhA, xlA);
        if (kk + 32 < kpb) { LOADW(wA, kk + 32); LOADX(xhA, xlA, kk + 32); }
        CHUNK_MMA(wB, xhB, xlB);
    }

#pragma unroll
    for (int mf = 0; mf < 2; mf++) {
        int n = n0 + mf * 16 + grp;
        float bv0 = use_bias ? bias[n] : 0.f;
        float bv8 = use_bias ? bias[n + 8] : 0.f;
#pragma unroll
        for (int bf = 0; bf < 8; bf++) {
            int b = bf * 8 + qid * 2;
            Out[(size_t)b * Ntot + n]           = acc[mf][bf][0] + bv0;
            Out[(size_t)(b + 1) * Ntot + n]     = acc[mf][bf][1] + bv0;
            Out[(size_t)b * Ntot + n + 8]       = acc[mf][bf][2] + bv8;
            Out[(size_t)(b + 1) * Ntot + n + 8] = acc[mf][bf][3] + bv8;
        }
    }
}

// ---------------- prep: embedding gather + hidden, both split to bf16 hi/lo ----------------
__global__ void k_prep(const int* __restrict__ seq, const float* __restrict__ table,
                       const float* __restrict__ last_hidden) {
    int i = blockIdx.x * 256 + threadIdx.x;   // B*H
    int b = i >> 10, h = i & 1023;
    float e = table[(size_t)seq[b] * HH + h];
    __nv_bfloat16 eh = __float2bfloat16(e);
    g_embh[i] = eh;
    g_embl[i] = __float2bfloat16(e - __bfloat162float(eh));
    float hd = last_hidden[i];
    __nv_bfloat16 hh = __float2bfloat16(hd);
    g_hidh[i] = hh;
    g_hidl[i] = __float2bfloat16(hd - __bfloat162float(hh));
}

// ---------------- GRU gates (8-way partial combine + bias folded) ----------------
__global__ void k_gate(const float* __restrict__ last_hidden, float* __restrict__ out_hidden,
                       const float* __restrict__ b_ih, const float* __restrict__ b_hh) {
    int i = blockIdx.x * 256 + threadIdx.x;   // B*H
    int b = i >> 10, h = i & 1023;
    const float* cpA = g_cpart;                        // gx partials [8][B][3H]
    const float* cpB = g_cpart + 8 * BB * 3 * HH;      // gh partials [8][B][3H]
    const int S = BB * 3 * HH;
    int base = b * 3 * HH;
    float xr = b_ih[h], xz = b_ih[HH + h], xn = b_ih[2 * HH + h];
    float hr = b_hh[h], hz = b_hh[HH + h], hn = b_hh[2 * HH + h];
#pragma unroll
    for (int s = 0; s < 8; s++) {
        xr += cpA[s * S + base + h];
        xz += cpA[s * S + base + HH + h];
        xn += cpA[s * S + base + 2 * HH + h];
        hr += cpB[s * S + base + h];
        hz += cpB[s * S + base + HH + h];
        hn += cpB[s * S + base + 2 * HH + h];
    }
    float r = 1.f / (1.f + expf(-(xr + hr)));
    float z = 1.f / (1.f + expf(-(xz + hz)));
    float n = tanhf(xn + r * hn);
    float hnew = (1.f - z) * n + z * last_hidden[i];
    out_hidden[i] = hnew;
    __nv_bfloat16 chi = __float2bfloat16(hnew);
    g_cinh[b * 2 * HH + h] = chi;
    g_cinl[b * 2 * HH + h] = __float2bfloat16(hnew - __bfloat162float(chi));
}

// ---------------- fused attention, 8-timestep batched online softmax ----------------
__global__ void __launch_bounds__(256) k_attn(const float* __restrict__ enc, const float* __restrict__ hnew) {
    int chunk = blockIdx.x, b = blockIdx.y;
    int tid = threadIdx.x;
    int wid = tid >> 5, lane = tid & 31;
    int h0 = tid * 4;
    __shared__ float red[8][8];       // [j][warp]
    __shared__ float score_sh[8];
    __shared__ float bc[9];           // rs, w[0..7]
    float4 hv = *(const float4*)&hnew[b * HH + h0];
    float m = -1e30f, s = 0.f;
    float c0 = 0.f, c1 = 0.f, c2 = 0.f, c3 = 0.f;
    int t0 = chunk * TPC;

    for (int tt = 0; tt < TPC; tt += 8) {
        float4 ev[8];
#pragma unroll
        for (int j = 0; j < 8; j++)
            ev[j] = *(const float4*)&enc[((size_t)(t0 + tt + j) * BB + b) * HH + h0];
        float p[8];
#pragma unroll
        for (int j = 0; j < 8; j++)
            p[j] = hv.x * ev[j].x + hv.y * ev[j].y + hv.z * ev[j].z + hv.w * ev[j].w;
#pragma unroll
        for (int o = 16; o; o >>= 1)
#pragma unroll
            for (int j = 0; j < 8; j++) p[j] += __shfl_xor_sync(0xffffffffu, p[j], o);
        if (lane == 0)
#pragma unroll
            for (int j = 0; j < 8; j++) red[j][wid] = p[j];
        __syncthreads();
        if (tid < 8) {
            float sc = red[tid][0] + red[tid][1] + red[tid][2] + red[tid][3]
                     + red[tid][4] + red[tid][5] + red[tid][6] + red[tid][7];
            score_sh[tid] = sc;
            g_scores[b * TT + t0 + tt + tid] = sc;
        }
        __syncthreads();
        if (tid == 0) {
            float bm = score_sh[0];
#pragma unroll
            for (int j = 1; j < 8; j++) bm = fmaxf(bm, score_sh[j]);
            float newm = fmaxf(m, bm);
            float rs = expf(m - newm);
            float ws = 0.f;
#pragma unroll
            for (int j = 0; j < 8; j++) { float wv = expf(score_sh[j] - newm); bc[1 + j] = wv; ws += wv; }
            s = s * rs + ws;
            m = newm;
            bc[0] = rs;
        }
        __syncthreads();
        float rs = bc[0];
        float w0 = bc[1], w1 = bc[2], w2 = bc[3], w3 = bc[4];
        float w4 = bc[5], w5 = bc[6], w6 = bc[7], w7 = bc[8];
        c0 = c0 * rs; c1 = c1 * rs; c2 = c2 * rs; c3 = c3 * rs;
        c0 += w0 * ev[0].x + w1 * ev[1].x + w2 * ev[2].x + w3 * ev[3].x
            + w4 * ev[4].x + w5 * ev[5].x + w6 * ev[6].x + w7 * ev[7].x;
        c1 += w0 * ev[0].y + w1 * ev[1].y + w2 * ev[2].y + w3 * ev[3].y
            + w4 * ev[4].y + w5 * ev[5].y + w6 * ev[6].y + w7 * ev[7].y;
        c2 += w0 * ev[0].z + w1 * ev[1].z + w2 * ev[2].z + w3 * ev[3].z
            + w4 * ev[4].z + w5 * ev[5].z + w6 * ev[6].z + w7 * ev[7].z;
        c3 += w0 * ev[0].w + w1 * ev[1].w + w2 * ev[2].w + w3 * ev[3].w
            + w4 * ev[4].w + w5 * ev[5].w + w6 * ev[6].w + w7 * ev[7].w;
        __syncthreads();   // protect red[][] reuse next iteration
    }
    *(float4*)&g_cctx[((size_t)chunk * BB + b) * HH + h0] = make_float4(c0, c1, c2, c3);
    if (tid == 0) { g_am[chunk * BB + b] = m; g_as[chunk * BB + b] = s; }
}

// ---------------- attention combine: merge partials, emit attn + bf16 context ----------------
__global__ void k_attn_comb(float* __restrict__ attn_out) {
    int b = blockIdx.x;
    int tid = threadIdx.x;
    float f[NCHUNK];
    float mstar = -1e30f;
#pragma unroll
    for (int c = 0; c < NCHUNK; c++) mstar = fmaxf(mstar, g_am[c * BB + b]);
    float sstar = 0.f;
#pragma unroll
    for (int c = 0; c < NCHUNK; c++) {
        f[c] = expf(g_am[c * BB + b] - mstar);
        sstar += g_as[c * BB + b] * f[c];
    }
    float inv = 1.f / sstar;
    int h0 = tid * 4;
    float a[4] = {0.f, 0.f, 0.f, 0.f};
#pragma unroll
    for (int c = 0; c < NCHUNK; c++) {
        float4 v = *(const float4*)&g_cctx[((size_t)c * BB + b) * HH + h0];
        a[0] += v.x * f[c]; a[1] += v.y * f[c]; a[2] += v.z * f[c]; a[3] += v.w * f[c];
    }
#pragma unroll
    for (int j = 0; j < 4; j++) {
        float cv = a[j] * inv;
        __nv_bfloat16 ch = __float2bfloat16(cv);
        g_cinh[b * 2 * HH + HH + h0 + j] = ch;
        g_cinl[b * 2 * HH + HH + h0 + j] = __float2bfloat16(cv - __bfloat162float(ch));
    }
#pragma unroll
    for (int j = 0; j < 4; j++) {
        int t = tid + j * 256;
        attn_out[b * TT + t] = expf(g_scores[b * TT + t] - mstar) * inv;
    }
}

// ---------------- concat combine: sum 16 partials + bias -> tanh -> bf16 hi/lo ----------------
__global__ void k_comb_concat(const float* __restrict__ concat_b) {
    int i = blockIdx.x * 256 + threadIdx.x;   // B*H
    int n = i & 1023;
    float v = concat_b[n];
#pragma unroll
    for (int s = 0; s < 16; s++) v += g_cpart[s * BB * HH + i];
    v = tanhf(v);
    __nv_bfloat16 hv = __float2bfloat16(v);
    g_couth[i] = hv;
    g_coutl[i] = __float2bfloat16(v - __bfloat162float(hv));
}

// ---------------- out combine: 2 partials + bias ----------------
__global__ void k_comb_out(const float* __restrict__ out_b, float* __restrict__ out) {
    int i = blockIdx.x * 256 + threadIdx.x;   // B*V
    int n = i % VV;
    out[i] = g_cpart[i] + g_cpart[BB * VV + i] + out_b[n];
}

// ---------------- launcher ----------------
extern "C" void kernel_launch(void* const* d_in, const int* in_sizes, int n_in,
                              void* d_out, int out_size) {
    const int*   seq         = (const int*)d_in[0];
    const float* last_hidden = (const float*)d_in[1];
    const float* enc         = (const float*)d_in[2];
    const float* emb_table   = (const float*)d_in[3];
    const float* w_ih        = (const float*)d_in[4];
    const float* w_hh        = (const float*)d_in[5];
    const float* b_ih        = (const float*)d_in[6];
    const float* b_hh        = (const float*)d_in[7];
    const float* concat_W    = (const float*)d_in[8];
    const float* concat_b    = (const float*)d_in[9];
    const float* out_W       = (const float*)d_in[10];
    const float* out_b       = (const float*)d_in[11];

    float* out        = (float*)d_out;             // [B, V]
    float* out_hidden = out + BB * VV;             // [1, B, H]
    float* out_attn   = out + BB * VV + BB * HH;   // [B, 1, T]

    float* p_cp;
    __nv_bfloat16 *p_embh, *p_embl, *p_hidh, *p_hidl, *p_cinh, *p_cinl, *p_couth, *p_coutl;
    cudaGetSymbolAddress((void**)&p_cp,    g_cpart);
    cudaGetSymbolAddress((void**)&p_embh,  g_embh);
    cudaGetSymbolAddress((void**)&p_embl,  g_embl);
    cudaGetSymbolAddress((void**)&p_hidh,  g_hidh);
    cudaGetSymbolAddress((void**)&p_hidl,  g_hidl);
    cudaGetSymbolAddress((void**)&p_cinh,  g_cinh);
    cudaGetSymbolAddress((void**)&p_cinl,  g_cinl);
    cudaGetSymbolAddress((void**)&p_couth, g_couth);
    cudaGetSymbolAddress((void**)&p_coutl, g_coutl);

    float* cpA = p_cp;                                // gx partials [8][B][3H]
    float* cpB = p_cp + 8 * BB * 3 * HH;              // gh partials [8][B][3H]

    // 1. prep: embedding + hidden -> bf16 hi/lo
    k_prep<<<256, 256>>>(seq, emb_table, last_hidden);
    // 2. gx = emb @ w_ih^T ; gh = h @ w_hh^T  (merged via z, ksplit=8 -> 384 CTAs)
    k_hmma<<<dim3(24, 8, 2), 128>>>(
        w_ih, w_hh, p_embh, p_embl, p_hidh, p_hidl, cpA, cpB, nullptr, nullptr, HH, 0);
    // 3. GRU gates -> h_new (folds 8-way partial-combine + bias)
    k_gate<<<256, 256>>>(last_hidden, out_hidden, b_ih, b_hh);
    // 4. fused attention, single enc pass (batched online softmax)
    k_attn<<<dim3(NCHUNK, BB), 256>>>(enc, out_hidden);
    k_attn_comb<<<BB, 256>>>(out_attn);
    // 5. concat gemm (K=2048, ksplit=16 -> 128 CTAs)
    k_hmma<<<dim3(8, 16, 1), 128>>>(
        concat_W, concat_W, p_cinh, p_cinl, p_cinh, p_cinl, p_cp, p_cp, nullptr, nullptr, 2 * HH, 0);
    k_comb_concat<<<256, 256>>>(concat_b);
    // 6. output gemm (K=1024, ksplit=2 -> 500 CTAs) + combine
    k_hmma<<<dim3(250, 2, 1), 128>>>(
        out_W, out_W, p_couth, p_coutl, p_couth, p_coutl, p_cp, p_cp, nullptr, nullptr, HH, 0);
    k_comb_out<<<8000, 256>>>(out_b, out);
}